// round 1
// baseline (speedup 1.0000x reference)
#include <cuda_runtime.h>
#include <float.h>
#include <math.h>

// Problem constants
#define BATCH 2
#define NPT   64      // user inputs per batch
#define CCH   256     // feature channels
#define KCLS  10      // classes

// Level geometry: HW = 4096,1024,256 ; Hdim = 64,32,16 ; img scale = 8,16,32
// K-split for template GEMM partials
// level0: KS=16 kchunk=256 ; level1: KS=8 kchunk=128 ; level2: KS=8 kchunk=32

__device__ __forceinline__ int heat_off(int level) {
    return level == 0 ? 0 : (level == 1 ? 524288 : 655360);
}
__device__ __forceinline__ int part_off(int level) {
    return level == 0 ? 0 : (level == 1 ? 524288 : 786432);
}

// Scratch (device globals; no allocation allowed)
__device__ float g_heat[BATCH * NPT * (4096 + 1024 + 256)];   // normalized heat, per level
__device__ float g_part[(16 + 8 + 8) * BATCH * NPT * CCH];    // K-split partial templates
__device__ float g_tmplT[3 * BATCH * CCH * NPT];              // template, transposed [lvl][b][c][n]
__device__ float g_cmax[2 * BATCH * KCLS * 5376];             // per-half class max partials

// int64-vs-int32 detection: labels are always in [1,10], so if the array is
// int64 little-endian, the int32 word at index 1 is the high word of label[0] == 0.
__device__ __forceinline__ bool detect64(const int* labels_i32) {
    return labels_i32[1] == 0;
}
__device__ __forceinline__ int geti(const int* p, int i, bool is64) {
    return p[is64 ? 2 * i : i];
}

// ---------------------------------------------------------------------------
// K0: Gaussian heat at level resolution, normalized. grid 384 = 3 lvl x 2 b x 64 n
// ---------------------------------------------------------------------------
__global__ void k_heat(const float* __restrict__ centers,
                       const int* __restrict__ idx_i32,
                       const int* __restrict__ labels_i32) {
    __shared__ float sh[4096];
    __shared__ float red[256];

    int blk = blockIdx.x;
    int level = blk >> 7;
    int rem = blk & 127;
    int b = rem >> 6, n = rem & 63;

    int hd = 64 >> level;          // 64, 32, 16
    int scale = 8 << level;        // 8, 16, 32
    int HW = hd * hd;

    bool is64 = detect64(labels_i32);
    bool valid = geti(idx_i32, b * NPT + n, is64) != -1;
    float cx = centers[(b * NPT + n) * 2 + 0];
    float cy = centers[(b * NPT + n) * 2 + 1];
    const float alpha = -0.5f / 9.0f;  // sigma = 3

    float sum = 0.f;
    for (int p = threadIdx.x; p < HW; p += blockDim.x) {
        int py = p / hd, px = p - py * hd;
        float x = px * (float)scale + 0.5f;
        float y = py * (float)scale + 0.5f;
        float dx = x - cx, dy = y - cy;
        float v = valid ? expf(alpha * (dx * dx + dy * dy)) : 0.f;
        sh[p] = v;
        sum += v;
    }
    red[threadIdx.x] = sum;
    __syncthreads();
    for (int s = 128; s > 0; s >>= 1) {
        if (threadIdx.x < s) red[threadIdx.x] += red[threadIdx.x + s];
        __syncthreads();
    }
    float inv = 1.0f / (red[0] + 1e-8f);

    float* hout = g_heat + heat_off(level) + (b * NPT + n) * HW;
    for (int p = threadIdx.x; p < HW; p += blockDim.x)
        hout[p] = sh[p] * inv;
}

// ---------------------------------------------------------------------------
// K1a: template GEMM partials. T[n][c] = sum_k heat[n][k] * feat[c][k]
// grid 256 blocks: lvl0 128 (4 ct x 16 ks x 2 b), lvl1 64, lvl2 64. 256 thr.
// ---------------------------------------------------------------------------
__global__ void k_tmpl_part(const float* __restrict__ x0,
                            const float* __restrict__ x1,
                            const float* __restrict__ x2) {
    __shared__ float As[64][33];
    __shared__ float Bs[64][33];

    int blk = blockIdx.x;
    int level, lb;
    if (blk < 128)      { level = 0; lb = blk; }
    else if (blk < 192) { level = 1; lb = blk - 128; }
    else                { level = 2; lb = blk - 192; }

    int ct, ks, b, kchunk, HW;
    if (level == 0) { ct = lb & 3; ks = (lb >> 2) & 15; b = lb >> 6; kchunk = 256; HW = 4096; }
    else            { ct = lb & 3; ks = (lb >> 2) & 7;  b = lb >> 5;
                      kchunk = (level == 1) ? 128 : 32; HW = (level == 1) ? 1024 : 256; }

    const float* feat = (level == 0) ? x0 : (level == 1) ? x1 : x2;
    const float* hb = g_heat + heat_off(level) + b * NPT * HW;
    const float* fb = feat + (size_t)(b * CCH + ct * 64) * HW;

    int ty = threadIdx.x >> 4, tx = threadIdx.x & 15;
    float acc[4][4];
#pragma unroll
    for (int i = 0; i < 4; i++)
#pragma unroll
        for (int j = 0; j < 4; j++) acc[i][j] = 0.f;

    int kbeg = ks * kchunk, kend = kbeg + kchunk;
    for (int k0 = kbeg; k0 < kend; k0 += 32) {
        for (int i = threadIdx.x; i < 64 * 32; i += 256) {
            int r = i >> 5, cc = i & 31;
            As[r][cc] = hb[r * HW + k0 + cc];
            Bs[r][cc] = fb[(size_t)r * HW + k0 + cc];
        }
        __syncthreads();
#pragma unroll 8
        for (int k = 0; k < 32; k++) {
            float a[4], bb[4];
#pragma unroll
            for (int i = 0; i < 4; i++) { a[i] = As[ty * 4 + i][k]; bb[i] = Bs[tx * 4 + i][k]; }
#pragma unroll
            for (int i = 0; i < 4; i++)
#pragma unroll
                for (int j = 0; j < 4; j++) acc[i][j] += a[i] * bb[j];
        }
        __syncthreads();
    }

    float* pp = g_part + part_off(level) + ((ks * BATCH + b) * NPT) * CCH;
#pragma unroll
    for (int i = 0; i < 4; i++) {
        int n = ty * 4 + i;
#pragma unroll
        for (int j = 0; j < 4; j++) {
            int c = ct * 64 + tx * 4 + j;
            pp[n * CCH + c] = acc[i][j];
        }
    }
}

// ---------------------------------------------------------------------------
// K1b: reduce partials over ks, write transposed template [lvl][b][c][n]
// grid 384 = 3 x 2 x 64 (n), 256 threads (c)
// ---------------------------------------------------------------------------
__global__ void k_tmpl_reduce() {
    int blk = blockIdx.x;
    int level = blk / 128;
    int rem = blk - level * 128;
    int b = rem >> 6, n = rem & 63;
    int KS = (level == 0) ? 16 : 8;
    int c = threadIdx.x;

    const float* pbase = g_part + part_off(level);
    float s = 0.f;
    for (int ks = 0; ks < KS; ks++)
        s += pbase[((ks * BATCH + b) * NPT + n) * CCH + c];

    g_tmplT[level * (BATCH * CCH * NPT) + (b * CCH + c) * NPT + n] = s;
}

// ---------------------------------------------------------------------------
// K2: correlation + per-class max partials + fused feat copy.
// grid 168: lvl0 128 (32 tiles x 2 b x 2 half), lvl1 32, lvl2 8. 128 threads.
// Each thread: 1 pixel, 32 n-accumulators (its n-half).
// ---------------------------------------------------------------------------
__global__ void k_cor(const float* __restrict__ x0,
                      const float* __restrict__ x1,
                      const float* __restrict__ x2,
                      const int* __restrict__ labels_i32,
                      float* __restrict__ out) {
    __shared__ float ts[CCH * 32];   // tmplT slice [c][n_local]
    __shared__ int lab[32];

    int blk = blockIdx.x;
    int level, lb;
    if (blk < 128)      { level = 0; lb = blk; }
    else if (blk < 160) { level = 1; lb = blk - 128; }
    else                { level = 2; lb = blk - 160; }

    int half = lb & 1;
    int b = (lb >> 1) & 1;
    int tile = lb >> 2;
    int HW = 4096 >> (2 * level);
    int oOff = (level == 0) ? 0 : (level == 1) ? 2179072 : 2723840;
    int q5376 = (level == 0) ? 0 : (level == 1) ? 4096 : 5120;
    const float* feat = (level == 0) ? x0 : (level == 1) ? x1 : x2;

    int tid = threadIdx.x;
    int n0 = half * 32;

    // stage template slice: ts[c*32 + j] = tmplT[lvl][b][c][n0+j]
    const float* tsrc = g_tmplT + level * (BATCH * CCH * NPT) + (size_t)b * CCH * NPT;
    for (int i = tid; i < CCH * 32; i += 128) {
        int c = i >> 5, j = i & 31;
        ts[i] = tsrc[c * NPT + n0 + j];
    }
    if (tid < 32) {
        bool is64 = detect64(labels_i32);
        lab[tid] = geti(labels_i32, b * NPT + n0 + tid, is64);
    }
    __syncthreads();

    int hw = tile * 128 + tid;
    const float* fb = feat + (size_t)b * CCH * HW + hw;
    float* ob = out + oOff + (size_t)b * (CCH + KCLS) * HW + hw;

    float acc[32];
#pragma unroll
    for (int i = 0; i < 32; i++) acc[i] = 0.f;

    float fc[4];
#pragma unroll
    for (int i = 0; i < 4; i++) fc[i] = fb[(size_t)i * HW];

    for (int c = 0; c < CCH; c += 4) {
        float fn[4] = {0.f, 0.f, 0.f, 0.f};
        if (c + 4 < CCH) {
#pragma unroll
            for (int i = 0; i < 4; i++) fn[i] = fb[(size_t)(c + 4 + i) * HW];
        }
#pragma unroll
        for (int u = 0; u < 4; u++) {
            float f = fc[u];
            if (half == 0) ob[(size_t)(c + u) * HW] = f;   // fused feat copy
            const float4* tp = (const float4*)&ts[(c + u) * 32];
#pragma unroll
            for (int j = 0; j < 8; j++) {
                float4 t = tp[j];
                acc[4 * j + 0] += t.x * f;
                acc[4 * j + 1] += t.y * f;
                acc[4 * j + 2] += t.z * f;
                acc[4 * j + 3] += t.w * f;
            }
        }
#pragma unroll
        for (int i = 0; i < 4; i++) fc[i] = fn[i];
    }

    // per-class max over this n-half; -FLT_MAX sentinel when class absent
    float* cm = g_cmax + ((size_t)(half * BATCH + b) * KCLS) * 5376 + q5376 + hw;
    for (int k = 1; k <= KCLS; k++) {
        float m = -FLT_MAX;
        for (int n = 0; n < 32; n++)
            if (lab[n] == k) m = fmaxf(m, acc[n]);
        cm[(size_t)(k - 1) * 5376] = m;
    }
}

// ---------------------------------------------------------------------------
// K3: combine halves, map absent-class sentinel -> 0, write class channels
// 107520 elements = B x 10 x 5376
// ---------------------------------------------------------------------------
__global__ void k_final(float* __restrict__ out) {
    int t = blockIdx.x * 256 + threadIdx.x;
    if (t >= BATCH * KCLS * 5376) return;
    int q = t % 5376;
    int rest = t / 5376;
    int k = rest % KCLS;
    int b = rest / KCLS;

    float a = g_cmax[((size_t)(0 * BATCH + b) * KCLS + k) * 5376 + q];
    float c = g_cmax[((size_t)(1 * BATCH + b) * KCLS + k) * 5376 + q];
    float m = fmaxf(a, c);
    if (m == -FLT_MAX) m = 0.f;

    int HW, hw, oOff;
    if (q < 4096)      { HW = 4096; hw = q;        oOff = 0; }
    else if (q < 5120) { HW = 1024; hw = q - 4096; oOff = 2179072; }
    else               { HW = 256;  hw = q - 5120; oOff = 2723840; }

    out[oOff + (size_t)(b * (CCH + KCLS) + CCH + k) * HW + hw] = m;
}

// ---------------------------------------------------------------------------
extern "C" void kernel_launch(void* const* d_in, const int* in_sizes, int n_in,
                              void* d_out, int out_size) {
    (void)in_sizes; (void)n_in; (void)out_size;
    const float* x0      = (const float*)d_in[0];
    const float* x1      = (const float*)d_in[1];
    const float* x2      = (const float*)d_in[2];
    const float* centers = (const float*)d_in[3];
    const int*   idx     = (const int*)d_in[4];
    const int*   labels  = (const int*)d_in[5];
    float* out = (float*)d_out;

    k_heat<<<384, 256>>>(centers, idx, labels);
    k_tmpl_part<<<256, 256>>>(x0, x1, x2);
    k_tmpl_reduce<<<384, 256>>>();
    k_cor<<<168, 128>>>(x0, x1, x2, labels, out);
    k_final<<<420, 256>>>(out);
}

// round 2
// speedup vs baseline: 1.0960x; 1.0960x over previous
#include <cuda_runtime.h>
#include <float.h>
#include <math.h>

// Problem constants
#define BATCH 2
#define NPT   64      // user inputs per batch
#define CCH   256     // feature channels
#define KCLS  10      // classes
#define NSPL  8       // n-split for correlation kernel
#define NLOC  8       // accumulators per thread (NPT / NSPL)

__device__ __forceinline__ int heat_off(int level) {
    return level == 0 ? 0 : (level == 1 ? 524288 : 655360);
}
__device__ __forceinline__ int part_off(int level) {
    return level == 0 ? 0 : (level == 1 ? 524288 : 786432);
}

// Scratch (device globals; no allocation allowed)
__device__ float g_heat[BATCH * NPT * (4096 + 1024 + 256)];   // normalized heat
__device__ float g_part[(16 + 8 + 8) * BATCH * NPT * CCH];    // K-split partial templates
__device__ float g_tmplT[3 * BATCH * CCH * NPT];              // template, [lvl][b][c][n]
__device__ float g_cmax[NSPL * BATCH * KCLS * 5376];          // per-npart class max partials

// int64-vs-int32 detection: labels in [1,10]; if int64 LE, word 1 == high(label0) == 0.
__device__ __forceinline__ bool detect64(const int* labels_i32) {
    return labels_i32[1] == 0;
}
__device__ __forceinline__ int geti(const int* p, int i, bool is64) {
    return p[is64 ? 2 * i : i];
}

// ---------------------------------------------------------------------------
// K0: Gaussian heat at level resolution, normalized. grid 384 = 3 lvl x 2 b x 64 n
// ---------------------------------------------------------------------------
__global__ void k_heat(const float* __restrict__ centers,
                       const int* __restrict__ idx_i32,
                       const int* __restrict__ labels_i32) {
    __shared__ float sh[4096];
    __shared__ float red[256];

    int blk = blockIdx.x;
    int level = blk >> 7;
    int rem = blk & 127;
    int b = rem >> 6, n = rem & 63;

    int hd = 64 >> level;
    int scale = 8 << level;
    int HW = hd * hd;

    bool is64 = detect64(labels_i32);
    bool valid = geti(idx_i32, b * NPT + n, is64) != -1;
    float cx = centers[(b * NPT + n) * 2 + 0];
    float cy = centers[(b * NPT + n) * 2 + 1];
    const float alpha = -0.5f / 9.0f;  // sigma = 3

    float sum = 0.f;
    for (int p = threadIdx.x; p < HW; p += blockDim.x) {
        int py = p / hd, px = p - py * hd;
        float x = px * (float)scale + 0.5f;
        float y = py * (float)scale + 0.5f;
        float dx = x - cx, dy = y - cy;
        float v = valid ? expf(alpha * (dx * dx + dy * dy)) : 0.f;
        sh[p] = v;
        sum += v;
    }
    red[threadIdx.x] = sum;
    __syncthreads();
    for (int s = 128; s > 0; s >>= 1) {
        if (threadIdx.x < s) red[threadIdx.x] += red[threadIdx.x + s];
        __syncthreads();
    }
    float inv = 1.0f / (red[0] + 1e-8f);

    float* hout = g_heat + heat_off(level) + (b * NPT + n) * HW;
    for (int p = threadIdx.x; p < HW; p += blockDim.x)
        hout[p] = sh[p] * inv;
}

// ---------------------------------------------------------------------------
// K1a: template GEMM partials. T[n][c] = sum_k heat[n][k] * feat[c][k]
// grid 256 blocks: lvl0 128 (4 ct x 16 ks x 2 b), lvl1 64, lvl2 64. 256 thr.
// ---------------------------------------------------------------------------
__global__ void k_tmpl_part(const float* __restrict__ x0,
                            const float* __restrict__ x1,
                            const float* __restrict__ x2) {
    __shared__ float As[64][33];
    __shared__ float Bs[64][33];

    int blk = blockIdx.x;
    int level, lb;
    if (blk < 128)      { level = 0; lb = blk; }
    else if (blk < 192) { level = 1; lb = blk - 128; }
    else                { level = 2; lb = blk - 192; }

    int ct, ks, b, kchunk, HW;
    if (level == 0) { ct = lb & 3; ks = (lb >> 2) & 15; b = lb >> 6; kchunk = 256; HW = 4096; }
    else            { ct = lb & 3; ks = (lb >> 2) & 7;  b = lb >> 5;
                      kchunk = (level == 1) ? 128 : 32; HW = (level == 1) ? 1024 : 256; }

    const float* feat = (level == 0) ? x0 : (level == 1) ? x1 : x2;
    const float* hb = g_heat + heat_off(level) + b * NPT * HW;
    const float* fb = feat + (size_t)(b * CCH + ct * 64) * HW;

    int ty = threadIdx.x >> 4, tx = threadIdx.x & 15;
    float acc[4][4];
#pragma unroll
    for (int i = 0; i < 4; i++)
#pragma unroll
        for (int j = 0; j < 4; j++) acc[i][j] = 0.f;

    int kbeg = ks * kchunk, kend = kbeg + kchunk;
    for (int k0 = kbeg; k0 < kend; k0 += 32) {
        for (int i = threadIdx.x; i < 64 * 32; i += 256) {
            int r = i >> 5, cc = i & 31;
            As[r][cc] = hb[r * HW + k0 + cc];
            Bs[r][cc] = fb[(size_t)r * HW + k0 + cc];
        }
        __syncthreads();
#pragma unroll 8
        for (int k = 0; k < 32; k++) {
            float a[4], bb[4];
#pragma unroll
            for (int i = 0; i < 4; i++) { a[i] = As[ty * 4 + i][k]; bb[i] = Bs[tx * 4 + i][k]; }
#pragma unroll
            for (int i = 0; i < 4; i++)
#pragma unroll
                for (int j = 0; j < 4; j++) acc[i][j] += a[i] * bb[j];
        }
        __syncthreads();
    }

    float* pp = g_part + part_off(level) + ((ks * BATCH + b) * NPT) * CCH;
#pragma unroll
    for (int i = 0; i < 4; i++) {
        int n = ty * 4 + i;
#pragma unroll
        for (int j = 0; j < 4; j++) {
            int c = ct * 64 + tx * 4 + j;
            pp[n * CCH + c] = acc[i][j];
        }
    }
}

// ---------------------------------------------------------------------------
// K1b: reduce partials over ks, write transposed template [lvl][b][c][n]
// ---------------------------------------------------------------------------
__global__ void k_tmpl_reduce() {
    int blk = blockIdx.x;
    int level = blk / 128;
    int rem = blk - level * 128;
    int b = rem >> 6, n = rem & 63;
    int KS = (level == 0) ? 16 : 8;
    int c = threadIdx.x;

    const float* pbase = g_part + part_off(level);
    float s = 0.f;
    for (int ks = 0; ks < KS; ks++)
        s += pbase[((ks * BATCH + b) * NPT + n) * CCH + c];

    g_tmplT[level * (BATCH * CCH * NPT) + (b * CCH + c) * NPT + n] = s;
}

// ---------------------------------------------------------------------------
// K2: correlation + per-class max partials + balanced fused feat copy.
// n split into NSPL=8 partitions of NLOC=8 accumulators.
// grid 672: lvl0 512 (32 tiles x 2 b x 8 part), lvl1 128, lvl2 32. 128 thr.
// Partition p also copies feat channel slice [32p, 32p+32) into out.
// ---------------------------------------------------------------------------
__global__ void k_cor(const float* __restrict__ x0,
                      const float* __restrict__ x1,
                      const float* __restrict__ x2,
                      const int* __restrict__ labels_i32,
                      float* __restrict__ out) {
    __shared__ float ts[CCH * NLOC];   // tmplT slice [c][n_local]
    __shared__ int lab[NLOC];

    int blk = blockIdx.x;
    int level, lb;
    if (blk < 512)      { level = 0; lb = blk; }
    else if (blk < 640) { level = 1; lb = blk - 512; }
    else                { level = 2; lb = blk - 640; }

    int part = lb & 7;
    int b = (lb >> 3) & 1;
    int tile = lb >> 4;
    int HW = 4096 >> (2 * level);
    int oOff = (level == 0) ? 0 : (level == 1) ? 2179072 : 2723840;
    int q5376 = (level == 0) ? 0 : (level == 1) ? 4096 : 5120;
    const float* feat = (level == 0) ? x0 : (level == 1) ? x1 : x2;

    int tid = threadIdx.x;
    int n0 = part * NLOC;

    // stage template slice: ts[c*NLOC + j] = tmplT[lvl][b][c][n0+j]
    const float* tsrc = g_tmplT + level * (BATCH * CCH * NPT) + (size_t)b * CCH * NPT;
    for (int i = tid; i < CCH * NLOC; i += 128) {
        int c = i >> 3, j = i & 7;
        ts[i] = tsrc[c * NPT + n0 + j];
    }
    if (tid < NLOC) {
        bool is64 = detect64(labels_i32);
        lab[tid] = geti(labels_i32, b * NPT + n0 + tid, is64);
    }
    __syncthreads();

    int hw = tile * 128 + tid;
    const float* fb = feat + (size_t)b * CCH * HW + hw;
    float* ob = out + oOff + (size_t)b * (CCH + KCLS) * HW + hw;

    float acc[NLOC];
#pragma unroll
    for (int i = 0; i < NLOC; i++) acc[i] = 0.f;

    int cpy0 = part * 32, cpy1 = cpy0 + 32;   // this block's feat-copy slice

    float fc[4];
#pragma unroll
    for (int i = 0; i < 4; i++) fc[i] = fb[(size_t)i * HW];

    for (int c = 0; c < CCH; c += 4) {
        float fn[4] = {0.f, 0.f, 0.f, 0.f};
        if (c + 4 < CCH) {
#pragma unroll
            for (int i = 0; i < 4; i++) fn[i] = fb[(size_t)(c + 4 + i) * HW];
        }
        bool docpy = (c >= cpy0) && (c < cpy1);
#pragma unroll
        for (int u = 0; u < 4; u++) {
            float f = fc[u];
            if (docpy) ob[(size_t)(c + u) * HW] = f;   // balanced fused feat copy
            const float4* tp = (const float4*)&ts[(c + u) * NLOC];
            float4 t0 = tp[0], t1 = tp[1];
            acc[0] += t0.x * f; acc[1] += t0.y * f;
            acc[2] += t0.z * f; acc[3] += t0.w * f;
            acc[4] += t1.x * f; acc[5] += t1.y * f;
            acc[6] += t1.z * f; acc[7] += t1.w * f;
        }
#pragma unroll
        for (int i = 0; i < 4; i++) fc[i] = fn[i];
    }

    // per-class max over this n-partition; -FLT_MAX sentinel when class absent
    float* cm = g_cmax + ((size_t)(part * BATCH + b) * KCLS) * 5376 + q5376 + hw;
#pragma unroll
    for (int k = 1; k <= KCLS; k++) {
        float m = -FLT_MAX;
#pragma unroll
        for (int n = 0; n < NLOC; n++)
            if (lab[n] == k) m = fmaxf(m, acc[n]);
        cm[(size_t)(k - 1) * 5376] = m;
    }
}

// ---------------------------------------------------------------------------
// K3: combine NSPL partials, map absent-class sentinel -> 0, write class ch.
// 107520 elements = B x 10 x 5376
// ---------------------------------------------------------------------------
__global__ void k_final(float* __restrict__ out) {
    int t = blockIdx.x * 256 + threadIdx.x;
    if (t >= BATCH * KCLS * 5376) return;
    int q = t % 5376;
    int rest = t / 5376;
    int k = rest % KCLS;
    int b = rest / KCLS;

    float m = -FLT_MAX;
#pragma unroll
    for (int p = 0; p < NSPL; p++)
        m = fmaxf(m, g_cmax[((size_t)(p * BATCH + b) * KCLS + k) * 5376 + q]);
    if (m == -FLT_MAX) m = 0.f;

    int HW, hw, oOff;
    if (q < 4096)      { HW = 4096; hw = q;        oOff = 0; }
    else if (q < 5120) { HW = 1024; hw = q - 4096; oOff = 2179072; }
    else               { HW = 256;  hw = q - 5120; oOff = 2723840; }

    out[oOff + (size_t)(b * (CCH + KCLS) + CCH + k) * HW + hw] = m;
}

// ---------------------------------------------------------------------------
extern "C" void kernel_launch(void* const* d_in, const int* in_sizes, int n_in,
                              void* d_out, int out_size) {
    (void)in_sizes; (void)n_in; (void)out_size;
    const float* x0      = (const float*)d_in[0];
    const float* x1      = (const float*)d_in[1];
    const float* x2      = (const float*)d_in[2];
    const float* centers = (const float*)d_in[3];
    const int*   idx     = (const int*)d_in[4];
    const int*   labels  = (const int*)d_in[5];
    float* out = (float*)d_out;

    k_heat<<<384, 256>>>(centers, idx, labels);
    k_tmpl_part<<<256, 256>>>(x0, x1, x2);
    k_tmpl_reduce<<<384, 256>>>();
    k_cor<<<672, 128>>>(x0, x1, x2, labels, out);
    k_final<<<420, 256>>>(out);
}

// round 3
// speedup vs baseline: 1.1317x; 1.0325x over previous
#include <cuda_runtime.h>
#include <float.h>
#include <math.h>

// Problem constants
#define BATCH 2
#define NPT   64      // user inputs per batch
#define CCH   256     // feature channels
#define KCLS  10      // classes
#define NSPL  8       // n-split for correlation kernel
#define NLOC  8       // accumulators per n-partition (NPT / NSPL)

__device__ __forceinline__ int heat_off(int level) {
    return level == 0 ? 0 : (level == 1 ? 524288 : 655360);
}
__device__ __forceinline__ int part_off(int level) {
    return level == 0 ? 0 : (level == 1 ? 524288 : 786432);
}

// Scratch (device globals; no allocation allowed)
__device__ float g_heat[BATCH * NPT * (4096 + 1024 + 256)];   // normalized heat
__device__ float g_part[(16 + 8 + 8) * BATCH * NPT * CCH];    // K-split partial templates
__device__ float g_tmplT[3 * BATCH * CCH * NPT];              // template, [lvl][b][c][n]
__device__ float g_cmax[NSPL * BATCH * KCLS * 5376];          // per-npart class max partials

// int64-vs-int32 detection: labels in [1,10]; if int64 LE, word 1 == high(label0) == 0.
__device__ __forceinline__ bool detect64(const int* labels_i32) {
    return labels_i32[1] == 0;
}
__device__ __forceinline__ int geti(const int* p, int i, bool is64) {
    return p[is64 ? 2 * i : i];
}

// ---------------------------------------------------------------------------
// K0: Gaussian heat at level resolution, normalized. grid 384 = 3 lvl x 2 b x 64 n
// ---------------------------------------------------------------------------
__global__ void k_heat(const float* __restrict__ centers,
                       const int* __restrict__ idx_i32,
                       const int* __restrict__ labels_i32) {
    __shared__ float sh[4096];
    __shared__ float red[256];

    int blk = blockIdx.x;
    int level = blk >> 7;
    int rem = blk & 127;
    int b = rem >> 6, n = rem & 63;

    int hd = 64 >> level;
    int scale = 8 << level;
    int HW = hd * hd;

    bool is64 = detect64(labels_i32);
    bool valid = geti(idx_i32, b * NPT + n, is64) != -1;
    float cx = centers[(b * NPT + n) * 2 + 0];
    float cy = centers[(b * NPT + n) * 2 + 1];
    const float alpha = -0.5f / 9.0f;  // sigma = 3

    float sum = 0.f;
    for (int p = threadIdx.x; p < HW; p += blockDim.x) {
        int py = p / hd, px = p - py * hd;
        float x = px * (float)scale + 0.5f;
        float y = py * (float)scale + 0.5f;
        float dx = x - cx, dy = y - cy;
        float v = valid ? expf(alpha * (dx * dx + dy * dy)) : 0.f;
        sh[p] = v;
        sum += v;
    }
    red[threadIdx.x] = sum;
    __syncthreads();
    for (int s = 128; s > 0; s >>= 1) {
        if (threadIdx.x < s) red[threadIdx.x] += red[threadIdx.x + s];
        __syncthreads();
    }
    float inv = 1.0f / (red[0] + 1e-8f);

    float* hout = g_heat + heat_off(level) + (b * NPT + n) * HW;
    for (int p = threadIdx.x; p < HW; p += blockDim.x)
        hout[p] = sh[p] * inv;
}

// ---------------------------------------------------------------------------
// K1a: template GEMM partials. T[n][c] = sum_k heat[n][k] * feat[c][k]
// grid 256 blocks: lvl0 128 (4 ct x 16 ks x 2 b), lvl1 64, lvl2 64. 256 thr.
// ---------------------------------------------------------------------------
__global__ void k_tmpl_part(const float* __restrict__ x0,
                            const float* __restrict__ x1,
                            const float* __restrict__ x2) {
    __shared__ float As[64][33];
    __shared__ float Bs[64][33];

    int blk = blockIdx.x;
    int level, lb;
    if (blk < 128)      { level = 0; lb = blk; }
    else if (blk < 192) { level = 1; lb = blk - 128; }
    else                { level = 2; lb = blk - 192; }

    int ct, ks, b, kchunk, HW;
    if (level == 0) { ct = lb & 3; ks = (lb >> 2) & 15; b = lb >> 6; kchunk = 256; HW = 4096; }
    else            { ct = lb & 3; ks = (lb >> 2) & 7;  b = lb >> 5;
                      kchunk = (level == 1) ? 128 : 32; HW = (level == 1) ? 1024 : 256; }

    const float* feat = (level == 0) ? x0 : (level == 1) ? x1 : x2;
    const float* hb = g_heat + heat_off(level) + b * NPT * HW;
    const float* fb = feat + (size_t)(b * CCH + ct * 64) * HW;

    int ty = threadIdx.x >> 4, tx = threadIdx.x & 15;
    float acc[4][4];
#pragma unroll
    for (int i = 0; i < 4; i++)
#pragma unroll
        for (int j = 0; j < 4; j++) acc[i][j] = 0.f;

    int kbeg = ks * kchunk, kend = kbeg + kchunk;
    for (int k0 = kbeg; k0 < kend; k0 += 32) {
        for (int i = threadIdx.x; i < 64 * 32; i += 256) {
            int r = i >> 5, cc = i & 31;
            As[r][cc] = hb[r * HW + k0 + cc];
            Bs[r][cc] = fb[(size_t)r * HW + k0 + cc];
        }
        __syncthreads();
#pragma unroll 8
        for (int k = 0; k < 32; k++) {
            float a[4], bb[4];
#pragma unroll
            for (int i = 0; i < 4; i++) { a[i] = As[ty * 4 + i][k]; bb[i] = Bs[tx * 4 + i][k]; }
#pragma unroll
            for (int i = 0; i < 4; i++)
#pragma unroll
                for (int j = 0; j < 4; j++) acc[i][j] += a[i] * bb[j];
        }
        __syncthreads();
    }

    float* pp = g_part + part_off(level) + ((ks * BATCH + b) * NPT) * CCH;
#pragma unroll
    for (int i = 0; i < 4; i++) {
        int n = ty * 4 + i;
#pragma unroll
        for (int j = 0; j < 4; j++) {
            int c = ct * 64 + tx * 4 + j;
            pp[n * CCH + c] = acc[i][j];
        }
    }
}

// ---------------------------------------------------------------------------
// K1b: reduce partials over ks, write transposed template [lvl][b][c][n]
// ---------------------------------------------------------------------------
__global__ void k_tmpl_reduce() {
    int blk = blockIdx.x;
    int level = blk / 128;
    int rem = blk - level * 128;
    int b = rem >> 6, n = rem & 63;
    int KS = (level == 0) ? 16 : 8;
    int c = threadIdx.x;

    const float* pbase = g_part + part_off(level);
    float s = 0.f;
    for (int ks = 0; ks < KS; ks++)
        s += pbase[((ks * BATCH + b) * NPT + n) * CCH + c];

    g_tmplT[level * (BATCH * CCH * NPT) + (b * CCH + c) * NPT + n] = s;
}

// ---------------------------------------------------------------------------
// K2: correlation + per-class max partials + balanced fused feat copy.
// 64-thread blocks, 2 pixels/thread (float2), NLOC=8 accumulator pairs.
// grid 672: lvl0 512 (32 tiles x 2 b x 8 part), lvl1 128 (8 tiles), lvl2 32 (2 tiles).
// Partition p also copies feat channel slice [32p, 32p+32) into out.
// ---------------------------------------------------------------------------
__global__ void __launch_bounds__(64) k_cor(
                      const float* __restrict__ x0,
                      const float* __restrict__ x1,
                      const float* __restrict__ x2,
                      const int* __restrict__ labels_i32,
                      float* __restrict__ out) {
    __shared__ float ts[CCH * NLOC];   // tmplT slice [c][n_local]
    __shared__ int lab[NLOC];

    int blk = blockIdx.x;
    int level, lb;
    if (blk < 512)      { level = 0; lb = blk; }
    else if (blk < 640) { level = 1; lb = blk - 512; }
    else                { level = 2; lb = blk - 640; }

    int part = lb & 7;
    int b = (lb >> 3) & 1;
    int tile = lb >> 4;
    int HW = 4096 >> (2 * level);
    int HW2 = HW >> 1;   // channel stride in float2
    int oOff = (level == 0) ? 0 : (level == 1) ? 2179072 : 2723840;
    int q5376 = (level == 0) ? 0 : (level == 1) ? 4096 : 5120;
    const float* feat = (level == 0) ? x0 : (level == 1) ? x1 : x2;

    int tid = threadIdx.x;
    int n0 = part * NLOC;

    // stage template slice: ts[c*NLOC + j] = tmplT[lvl][b][c][n0+j] (float2 copies)
    const float* tsrc = g_tmplT + level * (BATCH * CCH * NPT) + (size_t)b * CCH * NPT;
    for (int i = tid; i < CCH * NLOC / 2; i += 64) {
        int c = i >> 2, jj = i & 3;
        ((float2*)ts)[i] = *(const float2*)&tsrc[c * NPT + n0 + jj * 2];
    }
    if (tid < NLOC) {
        bool is64 = detect64(labels_i32);
        lab[tid] = geti(labels_i32, b * NPT + n0 + tid, is64);
    }
    __syncthreads();

    int hwp = tile * 64 + tid;           // pixel-pair index
    int hw = hwp * 2;
    const float2* fb2 = (const float2*)(feat + (size_t)b * CCH * HW) + hwp;
    float2* ob2 = (float2*)(out + oOff + (size_t)b * (CCH + KCLS) * HW) + hwp;

    float accx[NLOC], accy[NLOC];
#pragma unroll
    for (int i = 0; i < NLOC; i++) { accx[i] = 0.f; accy[i] = 0.f; }

    int cpy0 = part * 32, cpy1 = cpy0 + 32;   // this block's feat-copy slice

    float2 pre[4];
#pragma unroll
    for (int i = 0; i < 4; i++) pre[i] = fb2[(size_t)i * HW2];

#pragma unroll 4
    for (int c = 0; c < CCH; c++) {
        float2 f = pre[c & 3];
        int cn = c + 4;
        if (cn < CCH) pre[c & 3] = fb2[(size_t)cn * HW2];
        if (c >= cpy0 && c < cpy1) ob2[(size_t)c * HW2] = f;  // balanced fused copy
        const float4* tp = (const float4*)&ts[c * NLOC];
        float4 t0 = tp[0], t1 = tp[1];
        accx[0] += t0.x * f.x;  accy[0] += t0.x * f.y;
        accx[1] += t0.y * f.x;  accy[1] += t0.y * f.y;
        accx[2] += t0.z * f.x;  accy[2] += t0.z * f.y;
        accx[3] += t0.w * f.x;  accy[3] += t0.w * f.y;
        accx[4] += t1.x * f.x;  accy[4] += t1.x * f.y;
        accx[5] += t1.y * f.x;  accy[5] += t1.y * f.y;
        accx[6] += t1.z * f.x;  accy[6] += t1.z * f.y;
        accx[7] += t1.w * f.x;  accy[7] += t1.w * f.y;
    }

    // per-class max over this n-partition; -FLT_MAX sentinel when class absent
    float* cm = g_cmax + ((size_t)(part * BATCH + b) * KCLS) * 5376 + q5376 + hw;
#pragma unroll
    for (int k = 1; k <= KCLS; k++) {
        float mx = -FLT_MAX, my = -FLT_MAX;
#pragma unroll
        for (int n = 0; n < NLOC; n++)
            if (lab[n] == k) { mx = fmaxf(mx, accx[n]); my = fmaxf(my, accy[n]); }
        *(float2*)&cm[(size_t)(k - 1) * 5376] = make_float2(mx, my);
    }
}

// ---------------------------------------------------------------------------
// K3: combine NSPL partials, map absent-class sentinel -> 0, write class ch.
// 107520 elements = B x 10 x 5376
// ---------------------------------------------------------------------------
__global__ void k_final(float* __restrict__ out) {
    int t = blockIdx.x * 256 + threadIdx.x;
    if (t >= BATCH * KCLS * 5376) return;
    int q = t % 5376;
    int rest = t / 5376;
    int k = rest % KCLS;
    int b = rest / KCLS;

    float m = -FLT_MAX;
#pragma unroll
    for (int p = 0; p < NSPL; p++)
        m = fmaxf(m, g_cmax[((size_t)(p * BATCH + b) * KCLS + k) * 5376 + q]);
    if (m == -FLT_MAX) m = 0.f;

    int HW, hw, oOff;
    if (q < 4096)      { HW = 4096; hw = q;        oOff = 0; }
    else if (q < 5120) { HW = 1024; hw = q - 4096; oOff = 2179072; }
    else               { HW = 256;  hw = q - 5120; oOff = 2723840; }

    out[oOff + (size_t)(b * (CCH + KCLS) + CCH + k) * HW + hw] = m;
}

// ---------------------------------------------------------------------------
extern "C" void kernel_launch(void* const* d_in, const int* in_sizes, int n_in,
                              void* d_out, int out_size) {
    (void)in_sizes; (void)n_in; (void)out_size;
    const float* x0      = (const float*)d_in[0];
    const float* x1      = (const float*)d_in[1];
    const float* x2      = (const float*)d_in[2];
    const float* centers = (const float*)d_in[3];
    const int*   idx     = (const int*)d_in[4];
    const int*   labels  = (const int*)d_in[5];
    float* out = (float*)d_out;

    k_heat<<<384, 256>>>(centers, idx, labels);
    k_tmpl_part<<<256, 256>>>(x0, x1, x2);
    k_tmpl_reduce<<<384, 256>>>();
    k_cor<<<672, 64>>>(x0, x1, x2, labels, out);
    k_final<<<420, 256>>>(out);
}

// round 4
// speedup vs baseline: 1.2988x; 1.1476x over previous
#include <cuda_runtime.h>
#include <float.h>
#include <math.h>

// Problem constants
#define BATCH 2
#define NPT   64      // user inputs per batch
#define CCH   256     // feature channels
#define KCLS  10      // classes
#define NSPL  8       // class-max partitions (2 halves x 4 warps)
#define KT    32      // K-tile (channels per stage)

__device__ __forceinline__ int heat_off(int level) {
    return level == 0 ? 0 : (level == 1 ? 524288 : 655360);
}
__device__ __forceinline__ int part_off(int level) {
    return level == 0 ? 0 : (level == 1 ? 524288 : 786432);
}

// Scratch (device globals; no allocation allowed)
__device__ float g_heat[BATCH * NPT * (4096 + 1024 + 256)];   // normalized heat
__device__ float g_part[(16 + 8 + 8) * BATCH * NPT * CCH];    // K-split partial templates
__device__ float g_tmplT[3 * BATCH * CCH * NPT];              // template, [lvl][b][c][n]
__device__ float g_cmax[NSPL * BATCH * KCLS * 5376];          // per-partition class max

// int64-vs-int32 detection: labels in [1,10]; if int64 LE, word 1 == high(label0) == 0.
__device__ __forceinline__ bool detect64(const int* labels_i32) {
    return labels_i32[1] == 0;
}
__device__ __forceinline__ int geti(const int* p, int i, bool is64) {
    return p[is64 ? 2 * i : i];
}

// cp.async helpers
__device__ __forceinline__ void cp_async16(void* smem_dst, const void* gsrc) {
    unsigned s = (unsigned)__cvta_generic_to_shared(smem_dst);
    asm volatile("cp.async.cg.shared.global [%0], [%1], 16;\n" :: "r"(s), "l"(gsrc));
}
__device__ __forceinline__ void cp_commit() {
    asm volatile("cp.async.commit_group;\n" ::: "memory");
}
__device__ __forceinline__ void cp_wait1() {
    asm volatile("cp.async.wait_group 1;\n" ::: "memory");
}
__device__ __forceinline__ void cp_wait0() {
    asm volatile("cp.async.wait_group 0;\n" ::: "memory");
}

// ---------------------------------------------------------------------------
// K0: Gaussian heat at level resolution, normalized. grid 384 = 3 lvl x 2 b x 64 n
// ---------------------------------------------------------------------------
__global__ void k_heat(const float* __restrict__ centers,
                       const int* __restrict__ idx_i32,
                       const int* __restrict__ labels_i32) {
    __shared__ float sh[4096];
    __shared__ float red[256];

    int blk = blockIdx.x;
    int level = blk >> 7;
    int rem = blk & 127;
    int b = rem >> 6, n = rem & 63;

    int hd = 64 >> level;
    int scale = 8 << level;
    int HW = hd * hd;

    bool is64 = detect64(labels_i32);
    bool valid = geti(idx_i32, b * NPT + n, is64) != -1;
    float cx = centers[(b * NPT + n) * 2 + 0];
    float cy = centers[(b * NPT + n) * 2 + 1];
    const float alpha = -0.5f / 9.0f;  // sigma = 3

    float sum = 0.f;
    for (int p = threadIdx.x; p < HW; p += blockDim.x) {
        int py = p / hd, px = p - py * hd;
        float x = px * (float)scale + 0.5f;
        float y = py * (float)scale + 0.5f;
        float dx = x - cx, dy = y - cy;
        float v = valid ? __expf(alpha * (dx * dx + dy * dy)) : 0.f;
        sh[p] = v;
        sum += v;
    }
    red[threadIdx.x] = sum;
    __syncthreads();
    for (int s = 128; s > 0; s >>= 1) {
        if (threadIdx.x < s) red[threadIdx.x] += red[threadIdx.x + s];
        __syncthreads();
    }
    float inv = 1.0f / (red[0] + 1e-8f);

    float* hout = g_heat + heat_off(level) + (b * NPT + n) * HW;
    for (int p = threadIdx.x; p < HW; p += blockDim.x)
        hout[p] = sh[p] * inv;
}

// ---------------------------------------------------------------------------
// K1a: template GEMM partials. T[n][c] = sum_k heat[n][k] * feat[c][k]
// grid 256 blocks: lvl0 128 (4 ct x 16 ks x 2 b), lvl1 64, lvl2 64. 256 thr.
// ---------------------------------------------------------------------------
__global__ void k_tmpl_part(const float* __restrict__ x0,
                            const float* __restrict__ x1,
                            const float* __restrict__ x2) {
    __shared__ float As[64][33];
    __shared__ float Bs[64][33];

    int blk = blockIdx.x;
    int level, lb;
    if (blk < 128)      { level = 0; lb = blk; }
    else if (blk < 192) { level = 1; lb = blk - 128; }
    else                { level = 2; lb = blk - 192; }

    int ct, ks, b, kchunk, HW;
    if (level == 0) { ct = lb & 3; ks = (lb >> 2) & 15; b = lb >> 6; kchunk = 256; HW = 4096; }
    else            { ct = lb & 3; ks = (lb >> 2) & 7;  b = lb >> 5;
                      kchunk = (level == 1) ? 128 : 32; HW = (level == 1) ? 1024 : 256; }

    const float* feat = (level == 0) ? x0 : (level == 1) ? x1 : x2;
    const float* hb = g_heat + heat_off(level) + b * NPT * HW;
    const float* fb = feat + (size_t)(b * CCH + ct * 64) * HW;

    int ty = threadIdx.x >> 4, tx = threadIdx.x & 15;
    float acc[4][4];
#pragma unroll
    for (int i = 0; i < 4; i++)
#pragma unroll
        for (int j = 0; j < 4; j++) acc[i][j] = 0.f;

    int kbeg = ks * kchunk, kend = kbeg + kchunk;
    for (int k0 = kbeg; k0 < kend; k0 += 32) {
        for (int i = threadIdx.x; i < 64 * 32; i += 256) {
            int r = i >> 5, cc = i & 31;
            As[r][cc] = hb[r * HW + k0 + cc];
            Bs[r][cc] = fb[(size_t)r * HW + k0 + cc];
        }
        __syncthreads();
#pragma unroll 8
        for (int k = 0; k < 32; k++) {
            float a[4], bb[4];
#pragma unroll
            for (int i = 0; i < 4; i++) { a[i] = As[ty * 4 + i][k]; bb[i] = Bs[tx * 4 + i][k]; }
#pragma unroll
            for (int i = 0; i < 4; i++)
#pragma unroll
                for (int j = 0; j < 4; j++) acc[i][j] += a[i] * bb[j];
        }
        __syncthreads();
    }

    float* pp = g_part + part_off(level) + ((ks * BATCH + b) * NPT) * CCH;
#pragma unroll
    for (int i = 0; i < 4; i++) {
        int n = ty * 4 + i;
#pragma unroll
        for (int j = 0; j < 4; j++) {
            int c = ct * 64 + tx * 4 + j;
            pp[n * CCH + c] = acc[i][j];
        }
    }
}

// ---------------------------------------------------------------------------
// K1b: reduce partials over ks, write transposed template [lvl][b][c][n]
// ---------------------------------------------------------------------------
__global__ void k_tmpl_reduce() {
    int blk = blockIdx.x;
    int level = blk / 128;
    int rem = blk - level * 128;
    int b = rem >> 6, n = rem & 63;
    int KS = (level == 0) ? 16 : 8;
    int c = threadIdx.x;

    const float* pbase = g_part + part_off(level);
    float s = 0.f;
    for (int ks = 0; ks < KS; ks++)
        s += pbase[((ks * BATCH + b) * NPT + n) * CCH + c];

    g_tmplT[level * (BATCH * CCH * NPT) + (b * CCH + c) * NPT + n] = s;
}

// ---------------------------------------------------------------------------
// K2: correlation as cp.async-pipelined SMEM GEMM.
// Block = 128 thr (4 warps), tile = 32n(half) x 32px, K=256 in 8 stages of 32.
// Thread: 8 n-accumulators for 1 pixel (lane). Warp ty owns n-range [half*32+ty*8, +8).
// Partition id = half*4+ty (8 partitions). half==0 blocks also copy feat -> out.
// grid 672: lvl0 512 (128 px-tiles x 2 b x 2 half), lvl1 128, lvl2 32.
// ---------------------------------------------------------------------------
__global__ void __launch_bounds__(128) k_cor(
                      const float* __restrict__ x0,
                      const float* __restrict__ x1,
                      const float* __restrict__ x2,
                      const int* __restrict__ labels_i32,
                      float* __restrict__ out) {
    __shared__ float sA[2][KT][32];   // [buf][k][n_local]  (tmplT slice)
    __shared__ float sB[2][KT][32];   // [buf][k][px_local] (feat tile)
    __shared__ int lab[32];

    int blk = blockIdx.x;
    int level, lb;
    if (blk < 512)      { level = 0; lb = blk; }
    else if (blk < 640) { level = 1; lb = blk - 512; }
    else                { level = 2; lb = blk - 640; }

    int half = lb & 1;
    int b = (lb >> 1) & 1;
    int tile = lb >> 2;
    int HW = 4096 >> (2 * level);
    int px0 = tile * 32;
    int oOff = (level == 0) ? 0 : (level == 1) ? 2179072 : 2723840;
    int q5376 = (level == 0) ? 0 : (level == 1) ? 4096 : 5120;
    const float* feat = (level == 0) ? x0 : (level == 1) ? x1 : x2;

    int tid = threadIdx.x;
    int lane = tid & 31;
    int ty = tid >> 5;

    const float* tsrc = g_tmplT + level * (BATCH * CCH * NPT) + (size_t)b * CCH * NPT
                        + half * 32;                       // [c][n_local] base
    const float* fbase = feat + (size_t)b * CCH * HW + px0;
    float* obase = out + oOff + (size_t)b * (CCH + KCLS) * HW + px0;

    if (tid < 32) {
        bool is64 = detect64(labels_i32);
        lab[tid] = geti(labels_i32, b * NPT + half * 32 + tid, is64);
    }

    // stage indices: 256 float4 per operand per tile, 2 per thread
    int r0 = tid >> 3;                // row for j=0 (idx = tid)
    int q0 = (tid & 7) * 4;
    int r1 = (tid + 128) >> 3;        // row for j=1
    int q1 = q0;

    // prologue: stage tile 0 into buf 0
    cp_async16(&sA[0][r0][q0], tsrc + (size_t)r0 * NPT + q0);
    cp_async16(&sA[0][r1][q1], tsrc + (size_t)r1 * NPT + q1);
    cp_async16(&sB[0][r0][q0], fbase + (size_t)r0 * HW + q0);
    cp_async16(&sB[0][r1][q1], fbase + (size_t)r1 * HW + q1);
    cp_commit();

    float acc[8];
#pragma unroll
    for (int i = 0; i < 8; i++) acc[i] = 0.f;

    for (int kt = 0; kt < CCH / KT; kt++) {
        int buf = kt & 1;
        if (kt < CCH / KT - 1) {
            int c0 = (kt + 1) * KT;
            int nb = buf ^ 1;
            cp_async16(&sA[nb][r0][q0], tsrc + (size_t)(c0 + r0) * NPT + q0);
            cp_async16(&sA[nb][r1][q1], tsrc + (size_t)(c0 + r1) * NPT + q1);
            cp_async16(&sB[nb][r0][q0], fbase + (size_t)(c0 + r0) * HW + q0);
            cp_async16(&sB[nb][r1][q1], fbase + (size_t)(c0 + r1) * HW + q1);
            cp_commit();
            cp_wait1();
        } else {
            cp_wait0();
        }
        __syncthreads();

#pragma unroll
        for (int k = 0; k < KT; k++) {
            float bv = sB[buf][k][lane];
            float4 a0 = *(const float4*)&sA[buf][k][ty * 8];
            float4 a1 = *(const float4*)&sA[buf][k][ty * 8 + 4];
            acc[0] += a0.x * bv;
            acc[1] += a0.y * bv;
            acc[2] += a0.z * bv;
            acc[3] += a0.w * bv;
            acc[4] += a1.x * bv;
            acc[5] += a1.y * bv;
            acc[6] += a1.z * bv;
            acc[7] += a1.w * bv;
        }

        if (half == 0) {
            // fused feat copy from staged tile: 256 float4, 2 per thread
            int c0 = kt * KT;
            float4 v0 = *(const float4*)&sB[buf][r0][q0];
            float4 v1 = *(const float4*)&sB[buf][r1][q1];
            *(float4*)&obase[(size_t)(c0 + r0) * HW + q0] = v0;
            *(float4*)&obase[(size_t)(c0 + r1) * HW + q1] = v1;
        }
        __syncthreads();
    }

    // per-class max over this warp's 8 n; -FLT_MAX sentinel when class absent
    int nb0 = ty * 8;
    float* cm = g_cmax + ((size_t)((half * 4 + ty) * BATCH + b) * KCLS) * 5376
                + q5376 + px0 + lane;
#pragma unroll
    for (int k = 1; k <= KCLS; k++) {
        float m = -FLT_MAX;
#pragma unroll
        for (int j = 0; j < 8; j++)
            if (lab[nb0 + j] == k) m = fmaxf(m, acc[j]);
        cm[(size_t)(k - 1) * 5376] = m;
    }
}

// ---------------------------------------------------------------------------
// K3: combine NSPL partials, map absent-class sentinel -> 0, write class ch.
// 107520 elements = B x 10 x 5376
// ---------------------------------------------------------------------------
__global__ void k_final(float* __restrict__ out) {
    int t = blockIdx.x * 256 + threadIdx.x;
    if (t >= BATCH * KCLS * 5376) return;
    int q = t % 5376;
    int rest = t / 5376;
    int k = rest % KCLS;
    int b = rest / KCLS;

    float m = -FLT_MAX;
#pragma unroll
    for (int p = 0; p < NSPL; p++)
        m = fmaxf(m, g_cmax[((size_t)(p * BATCH + b) * KCLS + k) * 5376 + q]);
    if (m == -FLT_MAX) m = 0.f;

    int HW, hw, oOff;
    if (q < 4096)      { HW = 4096; hw = q;        oOff = 0; }
    else if (q < 5120) { HW = 1024; hw = q - 4096; oOff = 2179072; }
    else               { HW = 256;  hw = q - 5120; oOff = 2723840; }

    out[oOff + (size_t)(b * (CCH + KCLS) + CCH + k) * HW + hw] = m;
}

// ---------------------------------------------------------------------------
extern "C" void kernel_launch(void* const* d_in, const int* in_sizes, int n_in,
                              void* d_out, int out_size) {
    (void)in_sizes; (void)n_in; (void)out_size;
    const float* x0      = (const float*)d_in[0];
    const float* x1      = (const float*)d_in[1];
    const float* x2      = (const float*)d_in[2];
    const float* centers = (const float*)d_in[3];
    const int*   idx     = (const int*)d_in[4];
    const int*   labels  = (const int*)d_in[5];
    float* out = (float*)d_out;

    k_heat<<<384, 256>>>(centers, idx, labels);
    k_tmpl_part<<<256, 256>>>(x0, x1, x2);
    k_tmpl_reduce<<<384, 256>>>();
    k_cor<<<672, 128>>>(x0, x1, x2, labels, out);
    k_final<<<420, 256>>>(out);
}

// round 5
// speedup vs baseline: 1.3401x; 1.0318x over previous
#include <cuda_runtime.h>
#include <float.h>
#include <math.h>

// Problem constants
#define BATCH 2
#define NPT   64      // user inputs per batch
#define CCH   256     // feature channels
#define KCLS  10      // classes
#define KT    32      // K-tile per pipeline stage
#define NSPL  2       // class-max partitions in k_cor (2 warps)

// Level geometry: HW = 4096,1024,256
__device__ __forceinline__ int heatT_off(int level) {
    return level == 0 ? 0 : (level == 1 ? 524288 : 655360);   // [lvl][b][p][64]
}
__device__ __forceinline__ int part_off(int level) {
    return level == 0 ? 0 : (level == 1 ? 1048576 : 1572864);
}

// Scratch (device globals; no allocation allowed)
__device__ float g_heatT[BATCH * (4096 + 1024 + 256) * NPT];  // heat transposed [p][n]
__device__ float g_part[1835008];                             // K-split partial templates
__device__ float g_tmplT[3 * BATCH * CCH * NPT];              // template [lvl][b][c][n]
__device__ float g_cmax[NSPL * BATCH * KCLS * 5376];          // per-warp class max

// int64-vs-int32 detection: labels in [1,10]; if int64 LE, word 1 == high(label0) == 0.
__device__ __forceinline__ bool detect64(const int* labels_i32) {
    return labels_i32[1] == 0;
}
__device__ __forceinline__ int geti(const int* p, int i, bool is64) {
    return p[is64 ? 2 * i : i];
}

// cp.async helpers
__device__ __forceinline__ void cp_async16(void* smem_dst, const void* gsrc) {
    unsigned s = (unsigned)__cvta_generic_to_shared(smem_dst);
    asm volatile("cp.async.cg.shared.global [%0], [%1], 16;\n" :: "r"(s), "l"(gsrc));
}
__device__ __forceinline__ void cp_commit() {
    asm volatile("cp.async.commit_group;\n" ::: "memory");
}
__device__ __forceinline__ void cp_wait1() {
    asm volatile("cp.async.wait_group 1;\n" ::: "memory");
}
__device__ __forceinline__ void cp_wait0() {
    asm volatile("cp.async.wait_group 0;\n" ::: "memory");
}

// ---------------------------------------------------------------------------
// K0: Gaussian heat at level resolution, normalized, written TRANSPOSED
// g_heatT[lvl][b][p][n]. grid 384 = 3 lvl x 2 b x 64 n, 256 thr.
// ---------------------------------------------------------------------------
__global__ void k_heat(const float* __restrict__ centers,
                       const int* __restrict__ idx_i32,
                       const int* __restrict__ labels_i32) {
    __shared__ float sh[4096];
    __shared__ float red[256];

    int blk = blockIdx.x;
    int level = blk >> 7;
    int rem = blk & 127;
    int b = rem >> 6, n = rem & 63;

    int hd = 64 >> level;
    int scale = 8 << level;
    int HW = hd * hd;

    bool is64 = detect64(labels_i32);
    bool valid = geti(idx_i32, b * NPT + n, is64) != -1;
    float cx = centers[(b * NPT + n) * 2 + 0];
    float cy = centers[(b * NPT + n) * 2 + 1];
    const float alpha = -0.5f / 9.0f;  // sigma = 3

    float sum = 0.f;
    for (int p = threadIdx.x; p < HW; p += blockDim.x) {
        int py = p / hd, px = p - py * hd;
        float x = px * (float)scale + 0.5f;
        float y = py * (float)scale + 0.5f;
        float dx = x - cx, dy = y - cy;
        float v = valid ? __expf(alpha * (dx * dx + dy * dy)) : 0.f;
        sh[p] = v;
        sum += v;
    }
    red[threadIdx.x] = sum;
    __syncthreads();
    for (int s = 128; s > 0; s >>= 1) {
        if (threadIdx.x < s) red[threadIdx.x] += red[threadIdx.x + s];
        __syncthreads();
    }
    float inv = 1.0f / (red[0] + 1e-8f);

    float* hout = g_heatT + heatT_off(level) + (size_t)b * HW * NPT + n;
    for (int p = threadIdx.x; p < HW; p += blockDim.x)
        hout[(size_t)p * NPT] = sh[p] * inv;
}

// ---------------------------------------------------------------------------
// K1a: template GEMM partials, cp.async-pipelined.
// T[n][c] = sum_p heatT[p][n] * feat[c][p]. Block: 64n x 64c tile, k-chunked.
// grid 448: lvl0 256 (4ct x 32ks x 2b, kchunk=128), lvl1 128 (16ks, 64),
//           lvl2 64 (8ks, 32). 256 thr, 4x4 per thread.
// sA (heatT) staged via cp.async; sB (feat) transpose-staged via LDG+STS.
// ---------------------------------------------------------------------------
__global__ void __launch_bounds__(256) k_tmpl_part(
                            const float* __restrict__ x0,
                            const float* __restrict__ x1,
                            const float* __restrict__ x2) {
    __shared__ float sA[2][KT][68];   // [buf][k][n]
    __shared__ float sB[2][KT][68];   // [buf][k][c_local]

    int blk = blockIdx.x;
    int level, lb;
    if (blk < 256)      { level = 0; lb = blk; }
    else if (blk < 384) { level = 1; lb = blk - 256; }
    else                { level = 2; lb = blk - 384; }

    int ct, ks, b, kchunk, HW;
    if (level == 0)      { ct = lb & 3; ks = (lb >> 2) & 31; b = lb >> 7; kchunk = 128; HW = 4096; }
    else if (level == 1) { ct = lb & 3; ks = (lb >> 2) & 15; b = lb >> 6; kchunk = 64;  HW = 1024; }
    else                 { ct = lb & 3; ks = (lb >> 2) & 7;  b = lb >> 5; kchunk = 32;  HW = 256;  }
    int S = kchunk / KT;              // stages: 4 / 2 / 1
    int p0 = ks * kchunk;

    const float* feat = (level == 0) ? x0 : (level == 1) ? x1 : x2;
    const float* ha = g_heatT + heatT_off(level) + (size_t)b * HW * NPT;   // [p][n]

    int tid = threadIdx.x;
    int ty = tid >> 4, tx = tid & 15;

    // sA staging indices: 512 float4 per stage, 2 per thread
    int ar0 = tid >> 4, ac0 = (tid & 15) * 4;
    int ar1 = (tid + 256) >> 4, ac1 = ac0;

    // sB transpose staging: thread -> (c_row, kseg)
    int crow = tid >> 2;              // 0..63
    int kseg = (tid & 3) * 8;
    const float* fb = feat + (size_t)(b * CCH + ct * 64 + crow) * HW + p0 + kseg;

    float4 rb0, rb1;

    // prologue: stage 0
    cp_async16(&sA[0][ar0][ac0], ha + (size_t)(p0 + ar0) * NPT + ac0);
    cp_async16(&sA[0][ar1][ac1], ha + (size_t)(p0 + ar1) * NPT + ac1);
    cp_commit();
    rb0 = *(const float4*)(fb + 0);
    rb1 = *(const float4*)(fb + 4);
    cp_wait0();
#pragma unroll
    for (int i = 0; i < 4; i++) {
        sB[0][kseg + i][crow] = ((const float*)&rb0)[i];
        sB[0][kseg + 4 + i][crow] = ((const float*)&rb1)[i];
    }
    __syncthreads();

    float acc[4][4];
#pragma unroll
    for (int i = 0; i < 4; i++)
#pragma unroll
        for (int j = 0; j < 4; j++) acc[i][j] = 0.f;

    int n0 = ty * 4, c0 = tx * 4;

    for (int kt = 0; kt < S; kt++) {
        int buf = kt & 1, nb = buf ^ 1;
        if (kt < S - 1) {
            int pk = p0 + (kt + 1) * KT;
            cp_async16(&sA[nb][ar0][ac0], ha + (size_t)(pk + ar0) * NPT + ac0);
            cp_async16(&sA[nb][ar1][ac1], ha + (size_t)(pk + ar1) * NPT + ac1);
            cp_commit();
            rb0 = *(const float4*)(fb + (kt + 1) * KT + 0);
            rb1 = *(const float4*)(fb + (kt + 1) * KT + 4);
        }

#pragma unroll
        for (int k = 0; k < KT; k++) {
            float4 a = *(const float4*)&sA[buf][k][n0];
            float4 bb = *(const float4*)&sB[buf][k][c0];
            acc[0][0] += a.x * bb.x; acc[0][1] += a.x * bb.y;
            acc[0][2] += a.x * bb.z; acc[0][3] += a.x * bb.w;
            acc[1][0] += a.y * bb.x; acc[1][1] += a.y * bb.y;
            acc[1][2] += a.y * bb.z; acc[1][3] += a.y * bb.w;
            acc[2][0] += a.z * bb.x; acc[2][1] += a.z * bb.y;
            acc[2][2] += a.z * bb.z; acc[2][3] += a.z * bb.w;
            acc[3][0] += a.w * bb.x; acc[3][1] += a.w * bb.y;
            acc[3][2] += a.w * bb.z; acc[3][3] += a.w * bb.w;
        }

        if (kt < S - 1) {
            cp_wait0();
#pragma unroll
            for (int i = 0; i < 4; i++) {
                sB[nb][kseg + i][crow] = ((const float*)&rb0)[i];
                sB[nb][kseg + 4 + i][crow] = ((const float*)&rb1)[i];
            }
            __syncthreads();
        }
    }

    // write 4x4 partial
    float* pp = g_part + part_off(level) + (size_t)((ks * BATCH + b) * NPT) * CCH + ct * 64;
#pragma unroll
    for (int i = 0; i < 4; i++) {
        float4 v = make_float4(acc[i][0], acc[i][1], acc[i][2], acc[i][3]);
        *(float4*)&pp[(size_t)(n0 + i) * CCH + c0] = v;
    }
}

// ---------------------------------------------------------------------------
// K1b: reduce partials over ks, write transposed template [lvl][b][c][n]
// grid 384 = 3 x 2 x 64 (n), 256 thr (c)
// ---------------------------------------------------------------------------
__global__ void k_tmpl_reduce() {
    int blk = blockIdx.x;
    int level = blk / 128;
    int rem = blk - level * 128;
    int b = rem >> 6, n = rem & 63;
    int KS = (level == 0) ? 32 : (level == 1) ? 16 : 8;
    int c = threadIdx.x;

    const float* pbase = g_part + part_off(level);
    float s = 0.f;
    for (int ks = 0; ks < KS; ks++)
        s += pbase[(size_t)((ks * BATCH + b) * NPT + n) * CCH + c];

    g_tmplT[level * (BATCH * CCH * NPT) + (b * CCH + c) * NPT + n] = s;
}

// ---------------------------------------------------------------------------
// K2: correlation as cp.async GEMM, high FFMA density.
// Block = 64 thr (2 warps), tile = 64n x 32px, K=256 in 8 stages of 32.
// Warp w owns n in [w*32, w*32+32): per k: 8 broadcast LDS.128 + 1 LDS + 64 FFMA.
// Fused feat copy (full 256 ch) from staged sB. Class-max partition = warp id.
// grid 336: lvl0 256 (128 px-tiles x 2 b), lvl1 64, lvl2 16.
// ---------------------------------------------------------------------------
__global__ void __launch_bounds__(64) k_cor(
                      const float* __restrict__ x0,
                      const float* __restrict__ x1,
                      const float* __restrict__ x2,
                      const int* __restrict__ labels_i32,
                      float* __restrict__ out) {
    __shared__ float sA[2][KT][68];   // [buf][k=c][n]  (tmplT slice, 64 n)
    __shared__ float sB[2][KT][32];   // [buf][k=c][px]
    __shared__ int lab[NPT];

    int blk = blockIdx.x;
    int level, lb;
    if (blk < 256)      { level = 0; lb = blk; }
    else if (blk < 320) { level = 1; lb = blk - 256; }
    else                { level = 2; lb = blk - 320; }

    int b = lb & 1;
    int tile = lb >> 1;
    int HW = 4096 >> (2 * level);
    int px0 = tile * 32;
    int oOff = (level == 0) ? 0 : (level == 1) ? 2179072 : 2723840;
    int q5376 = (level == 0) ? 0 : (level == 1) ? 4096 : 5120;
    const float* feat = (level == 0) ? x0 : (level == 1) ? x1 : x2;

    int tid = threadIdx.x;
    int lane = tid & 31;
    int w = tid >> 5;

    const float* tsrc = g_tmplT + level * (BATCH * CCH * NPT) + (size_t)b * CCH * NPT;
    const float* fbase = feat + (size_t)b * CCH * HW + px0;
    float* obase = out + oOff + (size_t)b * (CCH + KCLS) * HW + px0;

    {
        bool is64 = detect64(labels_i32);
        lab[tid] = geti(labels_i32, b * NPT + tid, is64);   // tid < 64 == NPT
    }

    // sA: 512 f4/stage, 8 per thread. sB: 256 f4/stage, 4 per thread.
#define STAGE_CP(bufi, c0base)                                                   \
    {                                                                            \
        _Pragma("unroll")                                                        \
        for (int j = 0; j < 8; j++) {                                            \
            int idx = tid + j * 64;                                              \
            int r = idx >> 4, cc = (idx & 15) * 4;                               \
            cp_async16(&sA[bufi][r][cc], tsrc + (size_t)(c0base + r) * NPT + cc);\
        }                                                                        \
        _Pragma("unroll")                                                        \
        for (int j = 0; j < 4; j++) {                                            \
            int idx = tid + j * 64;                                              \
            int r = idx >> 3, cc = (idx & 7) * 4;                                \
            cp_async16(&sB[bufi][r][cc], fbase + (size_t)(c0base + r) * HW + cc);\
        }                                                                        \
        cp_commit();                                                             \
    }

    STAGE_CP(0, 0);

    float acc[32];
#pragma unroll
    for (int i = 0; i < 32; i++) acc[i] = 0.f;

    int n0 = w * 32;

    for (int kt = 0; kt < CCH / KT; kt++) {
        int buf = kt & 1;
        if (kt < CCH / KT - 1) {
            STAGE_CP(buf ^ 1, (kt + 1) * KT);
            cp_wait1();
        } else {
            cp_wait0();
        }
        __syncthreads();

#pragma unroll
        for (int k = 0; k < KT; k++) {
            float bv = sB[buf][k][lane];
            float4 a0 = *(const float4*)&sA[buf][k][n0];
            float4 a1 = *(const float4*)&sA[buf][k][n0 + 4];
            float4 a2 = *(const float4*)&sA[buf][k][n0 + 8];
            float4 a3 = *(const float4*)&sA[buf][k][n0 + 12];
            float4 a4 = *(const float4*)&sA[buf][k][n0 + 16];
            float4 a5 = *(const float4*)&sA[buf][k][n0 + 20];
            float4 a6 = *(const float4*)&sA[buf][k][n0 + 24];
            float4 a7 = *(const float4*)&sA[buf][k][n0 + 28];
            acc[0]  += a0.x * bv; acc[1]  += a0.y * bv; acc[2]  += a0.z * bv; acc[3]  += a0.w * bv;
            acc[4]  += a1.x * bv; acc[5]  += a1.y * bv; acc[6]  += a1.z * bv; acc[7]  += a1.w * bv;
            acc[8]  += a2.x * bv; acc[9]  += a2.y * bv; acc[10] += a2.z * bv; acc[11] += a2.w * bv;
            acc[12] += a3.x * bv; acc[13] += a3.y * bv; acc[14] += a3.z * bv; acc[15] += a3.w * bv;
            acc[16] += a4.x * bv; acc[17] += a4.y * bv; acc[18] += a4.z * bv; acc[19] += a4.w * bv;
            acc[20] += a5.x * bv; acc[21] += a5.y * bv; acc[22] += a5.z * bv; acc[23] += a5.w * bv;
            acc[24] += a6.x * bv; acc[25] += a6.y * bv; acc[26] += a6.z * bv; acc[27] += a6.w * bv;
            acc[28] += a7.x * bv; acc[29] += a7.y * bv; acc[30] += a7.z * bv; acc[31] += a7.w * bv;
        }

        // fused feat copy from staged tile
        {
            int c0 = kt * KT;
#pragma unroll
            for (int j = 0; j < 4; j++) {
                int idx = tid + j * 64;
                int r = idx >> 3, cc = (idx & 7) * 4;
                float4 v = *(const float4*)&sB[buf][r][cc];
                *(float4*)&obase[(size_t)(c0 + r) * HW + cc] = v;
            }
        }
        __syncthreads();
    }

    // per-class max over this warp's 32 n; -FLT_MAX sentinel when class absent
    float* cm = g_cmax + ((size_t)(w * BATCH + b) * KCLS) * 5376 + q5376 + px0 + lane;
#pragma unroll
    for (int k = 1; k <= KCLS; k++) {
        float m = -FLT_MAX;
#pragma unroll
        for (int j = 0; j < 32; j++)
            if (lab[n0 + j] == k) m = fmaxf(m, acc[j]);
        cm[(size_t)(k - 1) * 5376] = m;
    }
#undef STAGE_CP
}

// ---------------------------------------------------------------------------
// K3: combine NSPL partials, map absent-class sentinel -> 0, write class ch.
// ---------------------------------------------------------------------------
__global__ void k_final(float* __restrict__ out) {
    int t = blockIdx.x * 256 + threadIdx.x;
    if (t >= BATCH * KCLS * 5376) return;
    int q = t % 5376;
    int rest = t / 5376;
    int k = rest % KCLS;
    int b = rest / KCLS;

    float m = -FLT_MAX;
#pragma unroll
    for (int p = 0; p < NSPL; p++)
        m = fmaxf(m, g_cmax[((size_t)(p * BATCH + b) * KCLS + k) * 5376 + q]);
    if (m == -FLT_MAX) m = 0.f;

    int HW, hw, oOff;
    if (q < 4096)      { HW = 4096; hw = q;        oOff = 0; }
    else if (q < 5120) { HW = 1024; hw = q - 4096; oOff = 2179072; }
    else               { HW = 256;  hw = q - 5120; oOff = 2723840; }

    out[oOff + (size_t)(b * (CCH + KCLS) + CCH + k) * HW + hw] = m;
}

// ---------------------------------------------------------------------------
extern "C" void kernel_launch(void* const* d_in, const int* in_sizes, int n_in,
                              void* d_out, int out_size) {
    (void)in_sizes; (void)n_in; (void)out_size;
    const float* x0      = (const float*)d_in[0];
    const float* x1      = (const float*)d_in[1];
    const float* x2      = (const float*)d_in[2];
    const float* centers = (const float*)d_in[3];
    const int*   idx     = (const int*)d_in[4];
    const int*   labels  = (const int*)d_in[5];
    float* out = (float*)d_out;

    k_heat<<<384, 256>>>(centers, idx, labels);
    k_tmpl_part<<<448, 256>>>(x0, x1, x2);
    k_tmpl_reduce<<<384, 256>>>();
    k_cor<<<336, 64>>>(x0, x1, x2, labels, out);
    k_final<<<420, 256>>>(out);
}

// round 6
// speedup vs baseline: 1.7669x; 1.3185x over previous
#include <cuda_runtime.h>
#include <float.h>
#include <math.h>

// Problem constants
#define BATCH 2
#define NPT   64      // user inputs per batch
#define CCH   256     // feature channels
#define KCLS  10      // classes
#define KT    32      // K-tile per pipeline stage
#define NSPL  8       // class-max partitions in k_cor (2 halves x 4 warps)

// Separable Gaussian tables: g_ex[lvl][b][px][64n] (inv folded), g_ey[lvl][b][py][64n]
__device__ __forceinline__ int etab_off(int level, int b) {
    return level == 0 ? b * 4096 : (level == 1 ? 8192 + b * 2048 : 12288 + b * 1024);
}
__device__ __forceinline__ int part_off(int level) {
    return level == 0 ? 0 : (level == 1 ? 1048576 : 1572864);
}

// Scratch (device globals; no allocation allowed)
__device__ float g_ex[14336];
__device__ float g_ey[14336];
__device__ float g_part[1835008];                             // K-split partial templates
__device__ float g_tmplT[3 * BATCH * CCH * NPT];              // template [lvl][b][c][n]
__device__ float g_cmax[NSPL * BATCH * KCLS * 5376];          // per-partition class max

// int64-vs-int32 detection: labels in [1,10]; if int64 LE, word 1 == high(label0) == 0.
__device__ __forceinline__ bool detect64(const int* labels_i32) {
    return labels_i32[1] == 0;
}
__device__ __forceinline__ int geti(const int* p, int i, bool is64) {
    return p[is64 ? 2 * i : i];
}

// cp.async helpers
__device__ __forceinline__ void cp_async16(void* smem_dst, const void* gsrc) {
    unsigned s = (unsigned)__cvta_generic_to_shared(smem_dst);
    asm volatile("cp.async.cg.shared.global [%0], [%1], 16;\n" :: "r"(s), "l"(gsrc));
}
__device__ __forceinline__ void cp_commit() {
    asm volatile("cp.async.commit_group;\n" ::: "memory");
}
__device__ __forceinline__ void cp_wait1() {
    asm volatile("cp.async.wait_group 1;\n" ::: "memory");
}
__device__ __forceinline__ void cp_wait0() {
    asm volatile("cp.async.wait_group 0;\n" ::: "memory");
}

// ---------------------------------------------------------------------------
// K0: separable Gaussian tables. grid 384 = 3 lvl x 2 b x 64 n, 64 thr.
// ex[px][n] = exp(ax dx^2) / (Sx*Sy + 1e-8)  (0 if invalid); ey[py][n] = exp.
// ---------------------------------------------------------------------------
__global__ void k_heat(const float* __restrict__ centers,
                       const int* __restrict__ idx_i32,
                       const int* __restrict__ labels_i32) {
    __shared__ float redx[64], redy[64];

    int blk = blockIdx.x;
    int level = blk >> 7;
    int rem = blk & 127;
    int b = rem >> 6, n = rem & 63;

    int hd = 64 >> level;
    int scale = 8 << level;

    bool is64 = detect64(labels_i32);
    bool valid = geti(idx_i32, b * NPT + n, is64) != -1;
    float cx = centers[(b * NPT + n) * 2 + 0];
    float cy = centers[(b * NPT + n) * 2 + 1];
    const float alpha = -0.5f / 9.0f;  // sigma = 3

    int t = threadIdx.x;
    float exv = 0.f, eyv = 0.f;
    if (t < hd) {
        float coord = t * (float)scale + 0.5f;
        float dx = coord - cx, dy = coord - cy;
        exv = __expf(alpha * dx * dx);
        eyv = __expf(alpha * dy * dy);
    }
    redx[t] = exv; redy[t] = eyv;
    __syncthreads();
    for (int s = 32; s > 0; s >>= 1) {
        if (t < s) { redx[t] += redx[t + s]; redy[t] += redy[t + s]; }
        __syncthreads();
    }
    float inv = 1.0f / (redx[0] * redy[0] + 1e-8f);

    int off = etab_off(level, b);
    if (t < hd) {
        g_ex[off + t * 64 + n] = valid ? exv * inv : 0.f;
        g_ey[off + t * 64 + n] = eyv;
    }
}

// ---------------------------------------------------------------------------
// K1a: template GEMM partials, pipelined. T[n][c] = sum_p heat[n][p]*feat[c][p]
// sA computed on the fly from ex/ey tables; sB (feat) transpose-staged.
// grid 448: lvl0 256 (4ct x 32ks x 2b, kchunk=128), lvl1 128 (16ks, 64),
//           lvl2 64 (8ks, 32). 256 thr, 4x4 per thread.
// ---------------------------------------------------------------------------
__global__ void __launch_bounds__(256) k_tmpl_part(
                            const float* __restrict__ x0,
                            const float* __restrict__ x1,
                            const float* __restrict__ x2) {
    __shared__ float sA[2][KT][68];   // [buf][k][n]
    __shared__ float sB[2][KT][68];   // [buf][k][c_local]

    int blk = blockIdx.x;
    int level, lb;
    if (blk < 256)      { level = 0; lb = blk; }
    else if (blk < 384) { level = 1; lb = blk - 256; }
    else                { level = 2; lb = blk - 384; }

    int ct, ks, b, kchunk, HW;
    if (level == 0)      { ct = lb & 3; ks = (lb >> 2) & 31; b = lb >> 7; kchunk = 128; HW = 4096; }
    else if (level == 1) { ct = lb & 3; ks = (lb >> 2) & 15; b = lb >> 6; kchunk = 64;  HW = 1024; }
    else                 { ct = lb & 3; ks = (lb >> 2) & 7;  b = lb >> 5; kchunk = 32;  HW = 256;  }
    int S = kchunk / KT;              // stages: 4 / 2 / 1
    int p0 = ks * kchunk;
    int hdm = (64 >> level) - 1;      // px mask
    int hdsh = 6 - level;             // py shift

    const float* feat = (level == 0) ? x0 : (level == 1) ? x1 : x2;
    const float* exb = g_ex + etab_off(level, b);
    const float* eyb = g_ey + etab_off(level, b);

    int tid = threadIdx.x;
    int ty = tid >> 4, tx = tid & 15;

    // sA compute-staging: 512 f4 per stage, 2 per thread
    int ar0 = tid >> 4, anq = (tid & 15) * 4;
    int ar1 = ar0 + 16;

    // sB transpose staging: thread -> (c_row, kseg)
    int crow = tid >> 2;              // 0..63
    int kseg = (tid & 3) * 8;
    const float* fb = feat + (size_t)(b * CCH + ct * 64 + crow) * HW + p0 + kseg;

    float4 rb0, rb1, rex0, rey0, rex1, rey1;

#define LOAD_STAGE_REGS(pbase)                                            \
    {                                                                     \
        int pA0 = (pbase) + ar0, pA1 = (pbase) + ar1;                     \
        rex0 = *(const float4*)&exb[(pA0 & hdm) * 64 + anq];              \
        rey0 = *(const float4*)&eyb[(pA0 >> hdsh) * 64 + anq];            \
        rex1 = *(const float4*)&exb[(pA1 & hdm) * 64 + anq];              \
        rey1 = *(const float4*)&eyb[(pA1 >> hdsh) * 64 + anq];            \
    }
#define STORE_STAGE(bufi)                                                 \
    {                                                                     \
        *(float4*)&sA[bufi][ar0][anq] = make_float4(                      \
            rex0.x * rey0.x, rex0.y * rey0.y, rex0.z * rey0.z, rex0.w * rey0.w); \
        *(float4*)&sA[bufi][ar1][anq] = make_float4(                      \
            rex1.x * rey1.x, rex1.y * rey1.y, rex1.z * rey1.z, rex1.w * rey1.w); \
        _Pragma("unroll")                                                 \
        for (int i = 0; i < 4; i++) {                                     \
            sB[bufi][kseg + i][crow] = ((const float*)&rb0)[i];           \
            sB[bufi][kseg + 4 + i][crow] = ((const float*)&rb1)[i];       \
        }                                                                 \
    }

    // prologue: stage 0
    LOAD_STAGE_REGS(p0);
    rb0 = *(const float4*)(fb + 0);
    rb1 = *(const float4*)(fb + 4);
    STORE_STAGE(0);
    __syncthreads();

    float acc[4][4];
#pragma unroll
    for (int i = 0; i < 4; i++)
#pragma unroll
        for (int j = 0; j < 4; j++) acc[i][j] = 0.f;

    int n0 = ty * 4, c0 = tx * 4;

    for (int kt = 0; kt < S; kt++) {
        int buf = kt & 1, nb = buf ^ 1;
        if (kt < S - 1) {
            LOAD_STAGE_REGS(p0 + (kt + 1) * KT);
            rb0 = *(const float4*)(fb + (kt + 1) * KT + 0);
            rb1 = *(const float4*)(fb + (kt + 1) * KT + 4);
        }

#pragma unroll
        for (int k = 0; k < KT; k++) {
            float4 a = *(const float4*)&sA[buf][k][n0];
            float4 bb = *(const float4*)&sB[buf][k][c0];
            acc[0][0] += a.x * bb.x; acc[0][1] += a.x * bb.y;
            acc[0][2] += a.x * bb.z; acc[0][3] += a.x * bb.w;
            acc[1][0] += a.y * bb.x; acc[1][1] += a.y * bb.y;
            acc[1][2] += a.y * bb.z; acc[1][3] += a.y * bb.w;
            acc[2][0] += a.z * bb.x; acc[2][1] += a.z * bb.y;
            acc[2][2] += a.z * bb.z; acc[2][3] += a.z * bb.w;
            acc[3][0] += a.w * bb.x; acc[3][1] += a.w * bb.y;
            acc[3][2] += a.w * bb.z; acc[3][3] += a.w * bb.w;
        }

        if (kt < S - 1) {
            STORE_STAGE(nb);
            __syncthreads();
        }
    }
#undef LOAD_STAGE_REGS
#undef STORE_STAGE

    // write 4x4 partial
    float* pp = g_part + part_off(level) + (size_t)((ks * BATCH + b) * NPT) * CCH + ct * 64;
#pragma unroll
    for (int i = 0; i < 4; i++) {
        float4 v = make_float4(acc[i][0], acc[i][1], acc[i][2], acc[i][3]);
        *(float4*)&pp[(size_t)(n0 + i) * CCH + c0] = v;
    }
}

// ---------------------------------------------------------------------------
// K1b: reduce partials over ks, write transposed template [lvl][b][c][n]
// ---------------------------------------------------------------------------
__global__ void k_tmpl_reduce() {
    int blk = blockIdx.x;
    int level = blk / 128;
    int rem = blk - level * 128;
    int b = rem >> 6, n = rem & 63;
    int KS = (level == 0) ? 32 : (level == 1) ? 16 : 8;
    int c = threadIdx.x;

    const float* pbase = g_part + part_off(level);
    float s = 0.f;
    for (int ks = 0; ks < KS; ks++)
        s += pbase[(size_t)((ks * BATCH + b) * NPT + n) * CCH + c];

    g_tmplT[level * (BATCH * CCH * NPT) + (b * CCH + c) * NPT + n] = s;
}

// ---------------------------------------------------------------------------
// K2: correlation as cp.async GEMM. Block 128 thr (4 warps), tile 32n x 64px,
// 2 px/thread (float2). Warp w owns 8 n; per k: 2 LDS.128 + 1 LDS.64 + 16 FFMA.
// half==0 blocks copy feat -> out from staged sB. Partition = half*4 + w.
// grid 336: lvl0 256 (64 px-tiles x 2 b x 2 half), lvl1 64, lvl2 16.
// ---------------------------------------------------------------------------
__global__ void __launch_bounds__(128) k_cor(
                      const float* __restrict__ x0,
                      const float* __restrict__ x1,
                      const float* __restrict__ x2,
                      const int* __restrict__ labels_i32,
                      float* __restrict__ out) {
    __shared__ float sA[2][KT][32];   // [buf][k=c][n_local]
    __shared__ float sB[2][KT][64];   // [buf][k=c][px]
    __shared__ int lab[32];

    int blk = blockIdx.x;
    int level, lb;
    if (blk < 256)      { level = 0; lb = blk; }
    else if (blk < 320) { level = 1; lb = blk - 256; }
    else                { level = 2; lb = blk - 320; }

    int half = lb & 1;
    int b = (lb >> 1) & 1;
    int tile = lb >> 2;
    int HW = 4096 >> (2 * level);
    int px0 = tile * 64;
    int oOff = (level == 0) ? 0 : (level == 1) ? 2179072 : 2723840;
    int q5376 = (level == 0) ? 0 : (level == 1) ? 4096 : 5120;
    const float* feat = (level == 0) ? x0 : (level == 1) ? x1 : x2;

    int tid = threadIdx.x;
    int lane = tid & 31;
    int w = tid >> 5;

    const float* tsrc = g_tmplT + level * (BATCH * CCH * NPT) + (size_t)b * CCH * NPT
                        + half * 32;
    const float* fbase = feat + (size_t)b * CCH * HW + px0;
    float* obase = out + oOff + (size_t)b * (CCH + KCLS) * HW + px0;

    if (tid < 32) {
        bool is64 = detect64(labels_i32);
        lab[tid] = geti(labels_i32, b * NPT + half * 32 + tid, is64);
    }

    // sA: 256 f4/stage (2/thread); sB: 512 f4/stage (4/thread)
#define STAGE_CP(bufi, c0base)                                                    \
    {                                                                             \
        _Pragma("unroll")                                                         \
        for (int j = 0; j < 2; j++) {                                             \
            int idx = tid + j * 128;                                              \
            int r = idx >> 3, cq = (idx & 7) * 4;                                 \
            cp_async16(&sA[bufi][r][cq], tsrc + (size_t)((c0base) + r) * NPT + cq);\
        }                                                                         \
        _Pragma("unroll")                                                         \
        for (int j = 0; j < 4; j++) {                                             \
            int idx = tid + j * 128;                                              \
            int r = idx >> 4, cc = (idx & 15) * 4;                                \
            cp_async16(&sB[bufi][r][cc], fbase + (size_t)((c0base) + r) * HW + cc);\
        }                                                                         \
        cp_commit();                                                              \
    }

    STAGE_CP(0, 0);

    float accA[8], accB[8];
#pragma unroll
    for (int i = 0; i < 8; i++) { accA[i] = 0.f; accB[i] = 0.f; }

    int nw0 = w * 8;

    for (int kt = 0; kt < CCH / KT; kt++) {
        int buf = kt & 1;
        if (kt < CCH / KT - 1) {
            STAGE_CP(buf ^ 1, (kt + 1) * KT);
            cp_wait1();
        } else {
            cp_wait0();
        }
        __syncthreads();

#pragma unroll
        for (int k = 0; k < KT; k++) {
            float2 bv = *(const float2*)&sB[buf][k][lane * 2];
            float4 a0 = *(const float4*)&sA[buf][k][nw0];
            float4 a1 = *(const float4*)&sA[buf][k][nw0 + 4];
            accA[0] += a0.x * bv.x;  accB[0] += a0.x * bv.y;
            accA[1] += a0.y * bv.x;  accB[1] += a0.y * bv.y;
            accA[2] += a0.z * bv.x;  accB[2] += a0.z * bv.y;
            accA[3] += a0.w * bv.x;  accB[3] += a0.w * bv.y;
            accA[4] += a1.x * bv.x;  accB[4] += a1.x * bv.y;
            accA[5] += a1.y * bv.x;  accB[5] += a1.y * bv.y;
            accA[6] += a1.z * bv.x;  accB[6] += a1.z * bv.y;
            accA[7] += a1.w * bv.x;  accB[7] += a1.w * bv.y;
        }

        if (half == 0) {
            int c0 = kt * KT;
#pragma unroll
            for (int j = 0; j < 4; j++) {
                int idx = tid + j * 128;
                int r = idx >> 4, cc = (idx & 15) * 4;
                float4 v = *(const float4*)&sB[buf][r][cc];
                *(float4*)&obase[(size_t)(c0 + r) * HW + cc] = v;
            }
        }
        __syncthreads();
    }
#undef STAGE_CP

    // per-class max over this warp's 8 n; -FLT_MAX sentinel when class absent
    float* cm = g_cmax + ((size_t)((half * 4 + w) * BATCH + b) * KCLS) * 5376
                + q5376 + px0 + lane * 2;
#pragma unroll
    for (int k = 1; k <= KCLS; k++) {
        float mA = -FLT_MAX, mB = -FLT_MAX;
#pragma unroll
        for (int j = 0; j < 8; j++)
            if (lab[nw0 + j] == k) { mA = fmaxf(mA, accA[j]); mB = fmaxf(mB, accB[j]); }
        *(float2*)&cm[(size_t)(k - 1) * 5376] = make_float2(mA, mB);
    }
}

// ---------------------------------------------------------------------------
// K3: combine NSPL partials, map absent-class sentinel -> 0, write class ch.
// ---------------------------------------------------------------------------
__global__ void k_final(float* __restrict__ out) {
    int t = blockIdx.x * 256 + threadIdx.x;
    if (t >= BATCH * KCLS * 5376) return;
    int q = t % 5376;
    int rest = t / 5376;
    int k = rest % KCLS;
    int b = rest / KCLS;

    float m = -FLT_MAX;
#pragma unroll
    for (int p = 0; p < NSPL; p++)
        m = fmaxf(m, g_cmax[((size_t)(p * BATCH + b) * KCLS + k) * 5376 + q]);
    if (m == -FLT_MAX) m = 0.f;

    int HW, hw, oOff;
    if (q < 4096)      { HW = 4096; hw = q;        oOff = 0; }
    else if (q < 5120) { HW = 1024; hw = q - 4096; oOff = 2179072; }
    else               { HW = 256;  hw = q - 5120; oOff = 2723840; }

    out[oOff + (size_t)(b * (CCH + KCLS) + CCH + k) * HW + hw] = m;
}

// ---------------------------------------------------------------------------
extern "C" void kernel_launch(void* const* d_in, const int* in_sizes, int n_in,
                              void* d_out, int out_size) {
    (void)in_sizes; (void)n_in; (void)out_size;
    const float* x0      = (const float*)d_in[0];
    const float* x1      = (const float*)d_in[1];
    const float* x2      = (const float*)d_in[2];
    const float* centers = (const float*)d_in[3];
    const int*   idx     = (const int*)d_in[4];
    const int*   labels  = (const int*)d_in[5];
    float* out = (float*)d_out;

    k_heat<<<384, 64>>>(centers, idx, labels);
    k_tmpl_part<<<448, 256>>>(x0, x1, x2);
    k_tmpl_reduce<<<384, 256>>>();
    k_cor<<<336, 128>>>(x0, x1, x2, labels, out);
    k_final<<<420, 256>>>(out);
}